// round 13
// baseline (speedup 1.0000x reference)
#include <cuda_runtime.h>
#include <math.h>
#include <stdint.h>

#define H 2048
#define G 8192
#define NBQ 8
#define NBLK 148
#define NTH 928              // 28 consumer warps + 1 producer warp
#define NCW 28
#define NWI (NBLK*29)
#define BUFB 57344           // 7 rows * 8KB
#define NSLOT 3

// ---- smem byte offsets ----
#define OFF_BUF   0
#define OFF_H     172032     // 2048 floats
#define OFF_SP    180224     // 56 full-row gate sums
#define OFF_SP2   182016     // attn partials 14*16 floats
#define OFF_SL    183040     // logits scratch
#define OFF_SX    183104     // sampled xrow broadcast
#define OFF_MBAR  183168     // full[3], empty[3] mbarriers
#define SMEM_SZ   184320

// ---------------- device state ----------------
__device__ float d_xproj[18][G];
__device__ float d_bsum[G];
__device__ float d_c[H];
__device__ float d_hb[2][H];
__device__ float d_aw1[10][H];
__device__ float d_blkpart[10][160];
__device__ int   d_xrow;
__device__ unsigned g_count = 0;
__device__ unsigned g_flag  = 0;   // init barrier only
__device__ unsigned d_hcnt  = 0;   // phase-publish counter
__device__ unsigned d_sflag = 0;
__device__ unsigned d_acnt  = 0;
__device__ unsigned d_k0, d_k1;
__device__ float d_lp, d_ent;

struct P {
  const float *enc,*wih,*bih,*whh,*bhh,*wsoft,*bsoft,*bsnl,*w1,*w2,*v;
  float* out;
};

// ---------------- low-level helpers ----------------
__device__ __forceinline__ uint32_t s2u(const void* p){
  uint32_t a;
  asm("{ .reg .u64 t; cvta.to.shared.u64 t, %1; cvt.u32.u64 %0, t; }" : "=r"(a) : "l"(p));
  return a;
}
__device__ __forceinline__ unsigned atomAddRel(unsigned* p, unsigned v){
  unsigned old;
  asm volatile("atom.add.release.gpu.global.u32 %0,[%1],%2;"
               : "=r"(old) : "l"(p), "r"(v) : "memory");
  return old;
}
__device__ __forceinline__ unsigned ldAcq(unsigned* p){
  unsigned v;
  asm volatile("ld.acquire.gpu.global.u32 %0,[%1];" : "=r"(v) : "l"(p) : "memory");
  return v;
}
__device__ __forceinline__ void stRel(unsigned* p, unsigned v){
  asm volatile("st.release.gpu.global.u32 [%0],%1;" :: "l"(p), "r"(v) : "memory");
}
__device__ __forceinline__ void stRelax(unsigned* p, unsigned v){
  asm volatile("st.relaxed.gpu.global.u32 [%0],%1;" :: "l"(p), "r"(v) : "memory");
}
__device__ __forceinline__ void bar896(){
  asm volatile("bar.sync 1, 896;" ::: "memory");
}
__device__ __forceinline__ void mbar_init(uint32_t a, uint32_t cnt){
  asm volatile("mbarrier.init.shared.b64 [%0], %1;" :: "r"(a), "r"(cnt) : "memory");
}
__device__ __forceinline__ void mbar_expect_tx(uint32_t a, uint32_t bytes){
  asm volatile("mbarrier.arrive.expect_tx.shared.b64 _, [%0], %1;"
               :: "r"(a), "r"(bytes) : "memory");
}
__device__ __forceinline__ void mbar_arrive(uint32_t a){
  asm volatile("mbarrier.arrive.shared.b64 _, [%0];" :: "r"(a) : "memory");
}
__device__ __forceinline__ void mbar_wait_acq(uint32_t a, uint32_t par){
  asm volatile("{\n\t.reg .pred P;\n\t"
               "WL%=:\n\t"
               "mbarrier.try_wait.parity.acquire.cta.shared::cta.b64 P, [%0], %1, 0x989680;\n\t"
               "@P bra WD%=;\n\t"
               "bra WL%=;\n\t"
               "WD%=:\n\t}"
               :: "r"(a), "r"(par) : "memory");
}
__device__ __forceinline__ void mbar_wait_rlx(uint32_t a, uint32_t par){
  asm volatile("{\n\t.reg .pred P;\n\t"
               "WL%=:\n\t"
               "mbarrier.try_wait.parity.relaxed.cta.shared::cta.b64 P, [%0], %1, 0x989680;\n\t"
               "@P bra WD%=;\n\t"
               "bra WL%=;\n\t"
               "WD%=:\n\t}"
               :: "r"(a), "r"(par) : "memory");
}
__device__ __forceinline__ void bulk_g2s_pol(uint32_t dst, const void* src, uint32_t bytes,
                                             uint32_t mbar, uint64_t pol){
  asm volatile("cp.async.bulk.shared::cta.global.mbarrier::complete_tx::bytes.L2::cache_hint "
               "[%0], [%1], %2, [%3], %4;"
               :: "r"(dst), "l"(src), "r"(bytes), "r"(mbar), "l"(pol) : "memory");
}
__device__ __forceinline__ uint64_t pol_evict_last(){
  uint64_t p;
  asm("createpolicy.fractional.L2::evict_last.b64 %0, 1.0;" : "=l"(p));
  return p;
}
__device__ __forceinline__ uint64_t pol_evict_first(){
  uint64_t p;
  asm("createpolicy.fractional.L2::evict_first.b64 %0, 1.0;" : "=l"(p));
  return p;
}

// ---------------- threefry2x32 (JAX partitionable) ----------------
__device__ __forceinline__ void tf2(unsigned k0, unsigned k1, unsigned x0, unsigned x1,
                                    unsigned &o0, unsigned &o1){
  unsigned ks2 = k0 ^ k1 ^ 0x1BD11BDAu;
  x0 += k0; x1 += k1;
#define RND(r) { x0 += x1; x1 = (x1<<(r))|(x1>>(32-(r))); x1 ^= x0; }
  RND(13) RND(15) RND(26) RND(6)   x0 += k1;  x1 += ks2 + 1u;
  RND(17) RND(29) RND(16) RND(24)  x0 += ks2; x1 += k0  + 2u;
  RND(13) RND(15) RND(26) RND(6)   x0 += k0;  x1 += k1  + 3u;
  RND(17) RND(29) RND(16) RND(24)  x0 += k1;  x1 += ks2 + 4u;
  RND(13) RND(15) RND(26) RND(6)   x0 += ks2; x1 += k0  + 5u;
#undef RND
  o0 = x0; o1 = x1;
}

__device__ int do_sample(int n, const float* lg){
  unsigned nk0, nk1, s0, s1;
  tf2(d_k0, d_k1, 0u, 0u, nk0, nk1);
  tf2(d_k0, d_k1, 0u, 1u, s0,  s1);
  d_k0 = nk0; d_k1 = nk1;
  const float TINY = 1.17549435e-38f;
  float best = -INFINITY; int bi = 0;
  for (int i = 0; i < n; i++){
    unsigned o0, o1;
    tf2(s0, s1, 0u, (unsigned)i, o0, o1);
    unsigned bits = o0 ^ o1;
    float f = __uint_as_float((bits >> 9) | 0x3f800000u) - 1.0f;
    float u = fmaxf(TINY, f * (1.0f - TINY) + TINY);
    float z = -logf(-logf(u)) + lg[i];
    if (z > best){ best = z; bi = i; }
  }
  float mx = lg[0];
  for (int i = 1; i < n; i++) mx = fmaxf(mx, lg[i]);
  float se = 0.f;
  for (int i = 0; i < n; i++) se += expf(lg[i] - mx);
  float lse = logf(se);
  d_lp += -(lg[bi] - mx - lse);
  float e = 0.f;
  for (int i = 0; i < n; i++){ float ls = lg[i] - mx - lse; e -= ls * expf(ls); }
  d_ent += e;
  return bi;
}

__device__ __forceinline__ float sigf(float x){ return 1.f / (1.f + expf(-x)); }

// full-row warp dot (global or generic smem pointer)
__device__ __forceinline__ float wdot(const float* __restrict__ w,
                                      const float* __restrict__ shv, int lane){
  const float4* w4 = (const float4*)w;
  const float4* h4 = (const float4*)shv;
  float a = 0.f;
#pragma unroll
  for (int t = 0; t < 16; t++){
    float4 wv = w4[lane + 32*t];
    float4 hv = h4[lane + 32*t];
    a += wv.x*hv.x + wv.y*hv.y + wv.z*hv.z + wv.w*hv.w;
  }
#pragma unroll
  for (int o = 16; o; o >>= 1) a += __shfl_xor_sync(0xffffffffu, a, o);
  return a;
}

// ring cursor (R9-proven)
struct RC { int slot; unsigned ph;
  __device__ __forceinline__ void adv(){ if (++slot == NSLOT){ slot = 0; ph ^= 1u; } }
};

// =====================================================================
// consumer-side mega phase — R9 sync structure; full-row compute mapping.
// All 28 warps wait-full + arrive-empty on EVERY chunk (count 28).
// Warp group g = wi/7 COMPUTES chunks {g, g+4} (cell) / {g, g+4} of proj,
// one complete 8KB row (rloc = wi%7) per chunk.
// =====================================================================
__device__ void mega(const P& p, char* smem, int b, int tid, int wi, int lane, int hp,
                     int arow, int aidx, int attnL, int opsmp, int ub,
                     int xrow, unsigned sneed, int arcpos, unsigned spub,
                     unsigned aneed, unsigned hneed,
                     RC &rc, int qbase, int pbase, int abase,
                     uint32_t mb_full_base, uint32_t mb_empty_base){
  float* shh = (float*)(smem + OFF_H);
  float* sp  = (float*)(smem + OFF_SP);     // 56 full-row gate sums
  float* sp2 = (float*)(smem + OFF_SP2);
  float* sl  = (float*)(smem + OFF_SL);
  int*   sx  = (int*)(smem + OFF_SX);

  // wait for input h (one-sided acquire)
  if (tid == 0){
    unsigned v;
    do { v = ldAcq(&d_hcnt); } while ((int)(v - hneed) < 0);
  }
  bar896();
  for (int i = tid; i < H; i += 896) shh[i] = __ldcg(&d_hb[hp][i]);
  bar896();

  if (b > 0){
    int grp = wi / 7, rloc = wi % 7;
    // attn partials (warps 0..13) — R9 placement
    if (attnL > 0){
      if (wi < 14){
        int t = (b - 1) * 14 + wi;
        if (t < H){
          float s = wdot(p.w2 + (size_t)t * H, shh, lane);
          if (lane == 0){
            float vt = p.v[t];
            for (int i = 0; i < attnL; i++)
              sp2[wi*16 + i] = tanhf(__ldcg(&d_aw1[i][t]) + s) * vt;
          }
        } else if (lane == 0){
          for (int i = 0; i < attnL; i++) sp2[wi*16 + i] = 0.f;
        }
      }
      bar896();
      if (tid == 0){
        for (int i = 0; i < attnL; i++){
          float s = 0.f;
#pragma unroll
          for (int w = 0; w < 14; w++) s += sp2[w*16 + i];
          d_blkpart[i][b-1] = s;
        }
        atomAddRel(&d_acnt, 1u);
      }
    }
    // aw1 rows (warps 14..27) — R9 placement
    if (arow != -2 && wi >= 14){
      int r = abase + (wi - 14);
      float s = wdot(p.w1 + (size_t)r * H, shh, lane);
      if (lane == 0) d_aw1[aidx][r] = s;
    }
    // chunk walk (R9 cursor; all warps wait + arrive; owners compute full rows)
    int nch = (arow >= 0) ? 16 : 8;
    for (int c = 0; c < nch; c++){
      uint32_t fb = mb_full_base  + rc.slot * 8;
      uint32_t eb = mb_empty_base + rc.slot * 8;
      mbar_wait_acq(fb, rc.ph);
      int cc = c & 7;
      if ((cc & 3) == grp){
        const float* wrow = (const float*)(smem + OFF_BUF + rc.slot*BUFB + rloc*8192);
        float s = wdot(wrow, shh, lane);
        if (lane == 0){
          if (c < 8) sp[(cc >> 1)*14 + (cc & 1)*7 + rloc] = s;
          else       d_xproj[arow][pbase + cc*7 + rloc] = s;
        }
      }
      if (lane == 0) mbar_arrive(eb);
      rc.adv();
    }
    // sampled input row
    if (xrow < 0 && tid == 0){
      unsigned v;
      do { v = ldAcq(&d_sflag); } while ((int)(v - sneed) < 0);
      sx[0] = *((volatile int*)&d_xrow);
    }
    bar896();
    // gate combine: full-row sums, no partial reordering
    if (tid < 14){
      int j = tid, q = qbase + j;
      int xr = (xrow < 0) ? sx[0] : xrow;
      const float* xp = d_xproj[xr];
      float gi = sp[0*14 + j] + __ldcg(xp + q)       + d_bsum[q];
      float gf = sp[1*14 + j] + __ldcg(xp + q + H)   + d_bsum[q + H];
      float gg = sp[2*14 + j] + __ldcg(xp + q + 2*H) + d_bsum[q + 2*H];
      float go = sp[3*14 + j] + __ldcg(xp + q + 3*H) + d_bsum[q + 3*H];
      float c2 = sigf(gf) * d_c[q] + sigf(gi) * tanhf(gg);
      float h2 = sigf(go) * tanhf(c2);
      d_c[q] = c2;
      d_hb[hp ^ 1][q] = h2;
    }
  } else {
    // ---- block 0: control / sampling (R9 verbatim) ----
    if (attnL > 0){
      if (tid == 0){
        unsigned v;
        do { v = ldAcq(&d_acnt); } while ((int)(v - aneed) < 0);
      }
      bar896();
      if (wi < attnL){
        float a = 0.f;
        for (int k = lane; k < NBLK-1; k += 32) a += __ldcg(&d_blkpart[wi][k]);
#pragma unroll
        for (int o = 16; o; o >>= 1) a += __shfl_xor_sync(0xffffffffu, a, o);
        if (lane == 0) sl[wi] = a;
      }
      bar896();
      if (tid == 0){
        float lg[10];
        for (int i = 0; i < attnL; i++) lg[i] = 2.5f * tanhf(sl[i] / 5.0f);
        int idx = do_sample(attnL, lg);
        d_xrow = (idx < 2) ? 0 : (10 + idx - 2);
        p.out[arcpos] = (float)idx;
        stRel(&d_sflag, spub);
      }
    } else if (opsmp){
      if (wi < NBQ){
        float a = wdot(p.wsoft + (size_t)wi * H, shh, lane);
        if (lane == 0) sl[wi] = a;
      }
      bar896();
      if (tid == 0){
        float lg[NBQ];
        for (int i = 0; i < NBQ; i++){
          lg[i] = tanhf((sl[i] + p.bsoft[i]) / 5.0f);
          if (ub) lg[i] += p.bsnl[i];
        }
        int op = do_sample(NBQ, lg);
        d_xrow = 2 + op;
        p.out[arcpos] = (float)op;
        stRel(&d_sflag, spub);
      }
    }
  }

  // publish phase completion
  bar896();
  if (tid == 0) atomAddRel(&d_hcnt, 1u);
}

__global__ void __launch_bounds__(NTH, 1) ctrl_kernel(P p){
  extern __shared__ float shf[];
  char* smem = (char*)shf;
  int tid = threadIdx.x, wi = tid >> 5, lane = tid & 31;
  int b = blockIdx.x;
  unsigned gen   = *((volatile unsigned*)&g_flag);
  unsigned sbase = *((volatile unsigned*)&d_sflag);
  unsigned abase_cnt = *((volatile unsigned*)&d_acnt);
  unsigned hbase = *((volatile unsigned*)&d_hcnt);
  unsigned sc = 0, na = 0, hphase = 0;

  int qbase = (b > 0) ? min((b-1)*14, H - 14) : 0;
  int pbase = (b > 0) ? min((b-1)*56, G - 56) : 0;
  int awb   = (b > 0) ? min((b-1)*14, H - 14) : 0;

  uint32_t mb_full_base  = s2u(smem + OFF_MBAR);
  uint32_t mb_empty_base = s2u(smem + OFF_MBAR + 24);
  uint32_t buf_base      = s2u(smem + OFF_BUF);

  // ---- init ----
  if (tid == 0){
    for (int i = 0; i < NSLOT; i++){
      mbar_init(mb_full_base  + i*8, 1);
      mbar_init(mb_empty_base + i*8, NCW);   // all 28 warps arrive per chunk (R9)
    }
  }
  for (int i = b*NTH + tid; i < H; i += NBLK*NTH){
    d_c[i] = 0.f; d_hb[0][i] = 0.f; d_hb[1][i] = 0.f;
  }
  for (int i = b*NTH + tid; i < G; i += NBLK*NTH){
    d_bsum[i] = p.bih[i] + p.bhh[i];
    d_xproj[0][i] = 0.f;
  }
  if (b == 0 && tid == 0){
    d_k0 = 0u; d_k1 = 42u;
    d_lp = 0.f; d_ent = 0.f;
  }
  // encoder rows -> smem (ring area, init only), project through W_ih
  {
    float* se = (float*)smem;
    for (int i = tid; i < 9*H; i += NTH) se[i] = p.enc[i];
    __syncthreads();
    int gwa = b * 29 + wi;
    for (int r = gwa; r < G; r += NWI){
      const float4* w4 = (const float4*)(p.wih + (size_t)r * H);
      float acc[9];
#pragma unroll
      for (int e = 0; e < 9; e++) acc[e] = 0.f;
      for (int t = 0; t < 16; t++){
        float4 wv = __ldg(w4 + lane + 32*t);
#pragma unroll
        for (int e = 0; e < 9; e++){
          float4 xv = ((const float4*)se)[e*512 + lane + 32*t];
          acc[e] += wv.x*xv.x + wv.y*xv.y + wv.z*xv.z + wv.w*xv.w;
        }
      }
      for (int e = 0; e < 9; e++){
        float a = acc[e];
#pragma unroll
        for (int o = 16; o; o >>= 1) a += __shfl_xor_sync(0xffffffffu, a, o);
        if (lane == 0) d_xproj[1 + e][r] = a;
      }
    }
  }
  // init grid barrier (all threads)
  __syncthreads();
  if (tid == 0){
    unsigned target = gen + 1u;
    unsigned old = atomAddRel(&g_count, 1u);
    if (old == (unsigned)(NBLK - 1)){
      stRelax(&g_count, 0u);
      stRel(&g_flag, target);
    } else {
      unsigned v;
      do { v = ldAcq(&g_flag); } while ((int)(v - target) < 0);
    }
  }
  gen += 1u;
  __syncthreads();

  // ================= producer warp (R9 verbatim) =================
  if (wi == 28){
    if (b > 0 && lane == 0){
      uint64_t polL = pol_evict_last();
      uint64_t polF = pol_evict_first();
      RC pc; pc.slot = 0; pc.ph = 1u;
      for (int s = 0; s < 2; s++){
        for (int ph = 0; ph < 42; ph++){
          int proj = 0;
          int k = ph - 2;
          if (k >= 0 && (k % 5) == 0){ int L = 2 + k/5; if (L >= 3) proj = 1; }
          for (int c = 0; c < 8; c++){
            uint32_t eb = mb_empty_base + pc.slot*8;
            uint32_t fb = mb_full_base  + pc.slot*8;
            mbar_wait_rlx(eb, pc.ph);
            mbar_expect_tx(fb, BUFB);
            const float* src = p.whh + (size_t)((c>>1)*2048 + qbase + (c&1)*7) * H;
            bulk_g2s_pol(buf_base + pc.slot*BUFB, src, BUFB, fb, polL);
            pc.adv();
          }
          if (proj){
            for (int c = 0; c < 8; c++){
              uint32_t eb = mb_empty_base + pc.slot*8;
              uint32_t fb = mb_full_base  + pc.slot*8;
              mbar_wait_rlx(eb, pc.ph);
              mbar_expect_tx(fb, BUFB);
              const float* src = p.wih + (size_t)(pbase + c*7) * H;
              bulk_g2s_pol(buf_base + pc.slot*BUFB, src, BUFB, fb, polF);
              pc.adv();
            }
          }
        }
      }
      for (int i = 0; i < NSLOT; i++){
        mbar_wait_rlx(mb_empty_base + pc.slot*8, pc.ph);
        pc.adv();
      }
    }
    return;
  }

  // ================= consumer warps (tid < 896) =================
  RC rc; rc.slot = 0; rc.ph = 0u;
  int hp = 0;
  int p_ar = -2, p_ai = 0;
#define HNEED (hbase + 148u*hphase)
  for (int smp = 0; smp < 2; smp++){
    int ab = smp * 32;
    int ub = (smp == 0);
    mega(p, smem, b, tid, wi, lane, hp, -2, 0, 0, 0, 0, 1, 0, 0, 0, 0, HNEED,
         rc, qbase, pbase, awb, mb_full_base, mb_empty_base);
    hp ^= 1; hphase++;
    mega(p, smem, b, tid, wi, lane, hp, -1, 0, 0, 0, 0, 1, 0, 0, 0, 0, HNEED,
         rc, qbase, pbase, awb, mb_full_base, mb_empty_base);
    hp ^= 1; hphase++;
    p_ar = -1; p_ai = 1;
    for (int L = 2; L <= 9; L++){
      int base = ab + (L - 2) * 4;
      // ph1: cell (enc0) + pending proj/aw1
      mega(p, smem, b, tid, wi, lane, hp, p_ar, p_ai, 0, 0, 0, 1, 0, 0, 0, 0, HNEED,
           rc, qbase, pbase, awb, mb_full_base, mb_empty_base);
      hp ^= 1; hphase++;
      // ph2: cell + attn(h1); b0 samples idx0
      sc++; na++;
      mega(p, smem, b, tid, wi, lane, hp, -2, 0, L, 0, 0, -1, sbase + sc,
           base + 0, sbase + sc, abase_cnt + (NBLK-1)*na, HNEED,
           rc, qbase, pbase, awb, mb_full_base, mb_empty_base);
      hp ^= 1; hphase++;
      // ph3: cell + attn(h2); b0 samples idx1
      sc++; na++;
      mega(p, smem, b, tid, wi, lane, hp, -2, 0, L, 0, 0, -1, sbase + sc,
           base + 2, sbase + sc, abase_cnt + (NBLK-1)*na, HNEED,
           rc, qbase, pbase, awb, mb_full_base, mb_empty_base);
      hp ^= 1; hphase++;
      // ph4: cell; b0 samples op0 from h3
      sc++;
      mega(p, smem, b, tid, wi, lane, hp, -2, 0, 0, 1, ub, -1, sbase + sc,
           base + 1, sbase + sc, 0, HNEED,
           rc, qbase, pbase, awb, mb_full_base, mb_empty_base);
      hp ^= 1; hphase++;
      // ph5: anchor cell; b0 samples op1 from h4
      sc++;
      mega(p, smem, b, tid, wi, lane, hp, -2, 0, 0, 1, ub, -1, sbase + sc,
           base + 3, sbase + sc, 0, HNEED,
           rc, qbase, pbase, awb, mb_full_base, mb_empty_base);
      hp ^= 1; hphase++;
      if (L < 9){ p_ar = 10 + (L - 2); p_ai = L; }
      else      { p_ar = -2; p_ai = 0; }
    }
  }
#undef HNEED

  if (b == 0 && tid == 0){
    p.out[64] = d_lp;
    p.out[65] = d_ent;
  }
}

extern "C" void kernel_launch(void* const* d_in, const int* in_sizes, int n_in,
                              void* d_out, int out_size){
  P p;
  p.enc   = (const float*)d_in[0];
  p.wih   = (const float*)d_in[1];
  p.bih   = (const float*)d_in[2];
  p.whh   = (const float*)d_in[3];
  p.bhh   = (const float*)d_in[4];
  p.wsoft = (const float*)d_in[5];
  p.bsoft = (const float*)d_in[6];
  p.bsnl  = (const float*)d_in[7];
  p.w1    = (const float*)d_in[8];
  p.w2    = (const float*)d_in[9];
  p.v     = (const float*)d_in[10];
  p.out   = (float*)d_out;
  (void)in_sizes; (void)n_in; (void)out_size;

  cudaFuncSetAttribute(ctrl_kernel, cudaFuncAttributeMaxDynamicSharedMemorySize, SMEM_SZ);
  ctrl_kernel<<<NBLK, NTH, SMEM_SZ>>>(p);
}

// round 14
// speedup vs baseline: 1.2039x; 1.2039x over previous
#include <cuda_runtime.h>
#include <math.h>
#include <stdint.h>

#define H 2048
#define G 8192
#define NBQ 8
#define NBLK 148
#define NTH 928              // 28 consumer warps + 1 producer warp
#define NCW 28
#define NWI (NBLK*29)
#define BUFB 57344           // 7 rows * 8KB
#define NSLOT 3

// ---- smem byte offsets ----
#define OFF_BUF   0
#define OFF_H     172032     // 2048 floats
#define OFF_SP    180224     // 112 seg-partials (R9 layout)
#define OFF_SP2   182016     // attn partials 14*16 floats
#define OFF_SL    183040     // logits scratch
#define OFF_SX    183104     // sampled xrow broadcast
#define OFF_MBAR  183168     // full[3], empty[3] mbarriers
#define SMEM_SZ   184320

// ---------------- device state ----------------
__device__ float d_xproj[18][G];
__device__ float d_bsum[G];
__device__ float d_c[H];
__device__ float d_hb[2][H];
__device__ float d_aw1[10][H];
__device__ float d_blkpart[10][160];
__device__ int   d_xrow;
__device__ unsigned g_count = 0;
__device__ unsigned g_flag  = 0;   // init barrier only
__device__ unsigned d_hcnt  = 0;   // phase-publish counter
__device__ unsigned d_sflag = 0;
__device__ unsigned d_acnt  = 0;
__device__ unsigned d_k0, d_k1;
__device__ float d_lp, d_ent;

struct P {
  const float *enc,*wih,*bih,*whh,*bhh,*wsoft,*bsoft,*bsnl,*w1,*w2,*v;
  float* out;
};

// ---------------- low-level helpers ----------------
__device__ __forceinline__ uint32_t s2u(const void* p){
  uint32_t a;
  asm("{ .reg .u64 t; cvta.to.shared.u64 t, %1; cvt.u32.u64 %0, t; }" : "=r"(a) : "l"(p));
  return a;
}
__device__ __forceinline__ unsigned atomAddRel(unsigned* p, unsigned v){
  unsigned old;
  asm volatile("atom.add.release.gpu.global.u32 %0,[%1],%2;"
               : "=r"(old) : "l"(p), "r"(v) : "memory");
  return old;
}
__device__ __forceinline__ unsigned ldAcq(unsigned* p){
  unsigned v;
  asm volatile("ld.acquire.gpu.global.u32 %0,[%1];" : "=r"(v) : "l"(p) : "memory");
  return v;
}
__device__ __forceinline__ void stRel(unsigned* p, unsigned v){
  asm volatile("st.release.gpu.global.u32 [%0],%1;" :: "l"(p), "r"(v) : "memory");
}
__device__ __forceinline__ void stRelax(unsigned* p, unsigned v){
  asm volatile("st.relaxed.gpu.global.u32 [%0],%1;" :: "l"(p), "r"(v) : "memory");
}
__device__ __forceinline__ void bar896(){
  asm volatile("bar.sync 1, 896;" ::: "memory");
}
__device__ __forceinline__ void mbar_init(uint32_t a, uint32_t cnt){
  asm volatile("mbarrier.init.shared.b64 [%0], %1;" :: "r"(a), "r"(cnt) : "memory");
}
__device__ __forceinline__ void mbar_expect_tx(uint32_t a, uint32_t bytes){
  asm volatile("mbarrier.arrive.expect_tx.shared.b64 _, [%0], %1;"
               :: "r"(a), "r"(bytes) : "memory");
}
__device__ __forceinline__ void mbar_arrive(uint32_t a){
  asm volatile("mbarrier.arrive.shared.b64 _, [%0];" :: "r"(a) : "memory");
}
__device__ __forceinline__ void mbar_wait_acq(uint32_t a, uint32_t par){
  asm volatile("{\n\t.reg .pred P;\n\t"
               "WL%=:\n\t"
               "mbarrier.try_wait.parity.acquire.cta.shared::cta.b64 P, [%0], %1, 0x989680;\n\t"
               "@P bra WD%=;\n\t"
               "bra WL%=;\n\t"
               "WD%=:\n\t}"
               :: "r"(a), "r"(par) : "memory");
}
__device__ __forceinline__ void mbar_wait_rlx(uint32_t a, uint32_t par){
  asm volatile("{\n\t.reg .pred P;\n\t"
               "WL%=:\n\t"
               "mbarrier.try_wait.parity.relaxed.cta.shared::cta.b64 P, [%0], %1, 0x989680;\n\t"
               "@P bra WD%=;\n\t"
               "bra WL%=;\n\t"
               "WD%=:\n\t}"
               :: "r"(a), "r"(par) : "memory");
}
__device__ __forceinline__ void bulk_g2s_pol(uint32_t dst, const void* src, uint32_t bytes,
                                             uint32_t mbar, uint64_t pol){
  asm volatile("cp.async.bulk.shared::cta.global.mbarrier::complete_tx::bytes.L2::cache_hint "
               "[%0], [%1], %2, [%3], %4;"
               :: "r"(dst), "l"(src), "r"(bytes), "r"(mbar), "l"(pol) : "memory");
}
__device__ __forceinline__ uint64_t pol_evict_last(){
  uint64_t p;
  asm("createpolicy.fractional.L2::evict_last.b64 %0, 1.0;" : "=l"(p));
  return p;
}
__device__ __forceinline__ uint64_t pol_evict_first(){
  uint64_t p;
  asm("createpolicy.fractional.L2::evict_first.b64 %0, 1.0;" : "=l"(p));
  return p;
}

// ---------------- threefry2x32 (JAX partitionable) ----------------
__device__ __forceinline__ void tf2(unsigned k0, unsigned k1, unsigned x0, unsigned x1,
                                    unsigned &o0, unsigned &o1){
  unsigned ks2 = k0 ^ k1 ^ 0x1BD11BDAu;
  x0 += k0; x1 += k1;
#define RND(r) { x0 += x1; x1 = (x1<<(r))|(x1>>(32-(r))); x1 ^= x0; }
  RND(13) RND(15) RND(26) RND(6)   x0 += k1;  x1 += ks2 + 1u;
  RND(17) RND(29) RND(16) RND(24)  x0 += ks2; x1 += k0  + 2u;
  RND(13) RND(15) RND(26) RND(6)   x0 += k0;  x1 += k1  + 3u;
  RND(17) RND(29) RND(16) RND(24)  x0 += k1;  x1 += ks2 + 4u;
  RND(13) RND(15) RND(26) RND(6)   x0 += ks2; x1 += k0  + 5u;
#undef RND
  o0 = x0; o1 = x1;
}

__device__ int do_sample(int n, const float* lg){
  unsigned nk0, nk1, s0, s1;
  tf2(d_k0, d_k1, 0u, 0u, nk0, nk1);
  tf2(d_k0, d_k1, 0u, 1u, s0,  s1);
  d_k0 = nk0; d_k1 = nk1;
  const float TINY = 1.17549435e-38f;
  float best = -INFINITY; int bi = 0;
  for (int i = 0; i < n; i++){
    unsigned o0, o1;
    tf2(s0, s1, 0u, (unsigned)i, o0, o1);
    unsigned bits = o0 ^ o1;
    float f = __uint_as_float((bits >> 9) | 0x3f800000u) - 1.0f;
    float u = fmaxf(TINY, f * (1.0f - TINY) + TINY);
    float z = -logf(-logf(u)) + lg[i];
    if (z > best){ best = z; bi = i; }
  }
  float mx = lg[0];
  for (int i = 1; i < n; i++) mx = fmaxf(mx, lg[i]);
  float se = 0.f;
  for (int i = 0; i < n; i++) se += expf(lg[i] - mx);
  float lse = logf(se);
  d_lp += -(lg[bi] - mx - lse);
  float e = 0.f;
  for (int i = 0; i < n; i++){ float ls = lg[i] - mx - lse; e -= ls * expf(ls); }
  d_ent += e;
  return bi;
}

__device__ __forceinline__ float sigf(float x){ return 1.f / (1.f + expf(-x)); }

__device__ __forceinline__ float wdot(const float* __restrict__ w,
                                      const float* __restrict__ shv, int lane){
  const float4* w4 = (const float4*)w;
  const float4* h4 = (const float4*)shv;
  float a = 0.f;
#pragma unroll
  for (int t = 0; t < 16; t++){
    float4 wv = w4[lane + 32*t];
    float4 hv = h4[lane + 32*t];
    a += wv.x*hv.x + wv.y*hv.y + wv.z*hv.z + wv.w*hv.w;
  }
#pragma unroll
  for (int o = 16; o; o >>= 1) a += __shfl_xor_sync(0xffffffffu, a, o);
  return a;
}

// ring cursor (R9-proven)
struct RC { int slot; unsigned ph;
  __device__ __forceinline__ void adv(){ if (++slot == NSLOT){ slot = 0; ph ^= 1u; } }
};

// =====================================================================
// consumer-side mega phase — R9 structure + {conditional shh, aw1 post-
// loop, registerized c/bsum}.
// =====================================================================
__device__ void mega(const P& p, char* smem, int b, int tid, int wi, int lane, int hp,
                     int arow, int aidx, int attnL, int opsmp, int ub,
                     int xrow, unsigned sneed, int arcpos, unsigned spub,
                     unsigned aneed, unsigned hneed,
                     RC &rc, int qbase, int pbase, int abase,
                     uint32_t mb_full_base, uint32_t mb_empty_base,
                     float &creg, const float* bs){
  float* shh = (float*)(smem + OFF_H);
  float* sp  = (float*)(smem + OFF_SP);
  float* sp2 = (float*)(smem + OFF_SP2);
  float* sl  = (float*)(smem + OFF_SL);
  int*   sx  = (int*)(smem + OFF_SX);

  // wait for input h (one-sided acquire)
  if (tid == 0){
    unsigned v;
    do { v = ldAcq(&d_hcnt); } while ((int)(v - hneed) < 0);
  }
  bar896();

  bool need_shh = (b == 0) ? (opsmp != 0) : (attnL > 0 || arow != -2);
  if (need_shh){
    for (int i = tid; i < H; i += 896) shh[i] = __ldcg(&d_hb[hp][i]);
    bar896();
  }

  if (b > 0){
    int seg = wi & 3, row7 = wi >> 2;
    // h segment into registers (from shh when staged, else direct gmem; same bits)
    float4 hr[4];
    if (need_shh){
      const float4* h4 = (const float4*)(shh + seg*512);
#pragma unroll
      for (int t = 0; t < 4; t++) hr[t] = h4[lane + 32*t];
    } else {
      const float4* h4 = (const float4*)(&d_hb[hp][seg*512]);
#pragma unroll
      for (int t = 0; t < 4; t++) hr[t] = __ldcg(h4 + lane + 32*t);
    }
    // attn partials (warps 0..13) — early publish path for block 0
    if (attnL > 0){
      if (wi < 14){
        int t = (b - 1) * 14 + wi;
        if (t < H){
          float s = wdot(p.w2 + (size_t)t * H, shh, lane);
          if (lane == 0){
            float vt = p.v[t];
            for (int i = 0; i < attnL; i++)
              sp2[wi*16 + i] = tanhf(__ldcg(&d_aw1[i][t]) + s) * vt;
          }
        } else if (lane == 0){
          for (int i = 0; i < attnL; i++) sp2[wi*16 + i] = 0.f;
        }
      }
      bar896();
      if (tid == 0){
        for (int i = 0; i < attnL; i++){
          float s = 0.f;
#pragma unroll
          for (int w = 0; w < 14; w++) s += sp2[w*16 + i];
          d_blkpart[i][b-1] = s;
        }
        atomAddRel(&d_acnt, 1u);
      }
    }
    // chunk walk (R9 cursor + seg-split consumption)
    int nch = (arow >= 0) ? 16 : 8;
    for (int c = 0; c < nch; c++){
      uint32_t fb = mb_full_base  + rc.slot * 8;
      uint32_t eb = mb_empty_base + rc.slot * 8;
      mbar_wait_acq(fb, rc.ph);
      const float4* w4 = (const float4*)(smem + OFF_BUF + rc.slot*BUFB
                                         + row7*8192 + seg*2048);
      float a = 0.f;
#pragma unroll
      for (int t = 0; t < 4; t++){
        float4 wv = w4[lane + 32*t];
        a += wv.x*hr[t].x + wv.y*hr[t].y + wv.z*hr[t].z + wv.w*hr[t].w;
      }
#pragma unroll
      for (int o = 16; o; o >>= 1) a += __shfl_xor_sync(0xffffffffu, a, o);
      if (lane == 0){
        float* dst = (c < 8) ? sp : (sp + 56*4);
        dst[((c & 7)*7 + row7)*4 + seg] = a;
        mbar_arrive(eb);
      }
      rc.adv();
    }
    // aw1 rows: after chunk loop (off the ring critical path)
    if (arow != -2 && wi >= 14){
      int r = abase + (wi - 14);
      float s = wdot(p.w1 + (size_t)r * H, shh, lane);
      if (lane == 0) d_aw1[aidx][r] = s;
    }
    // sampled input row
    if (xrow < 0 && tid == 0){
      unsigned v;
      do { v = ldAcq(&d_sflag); } while ((int)(v - sneed) < 0);
      sx[0] = *((volatile int*)&d_xrow);
    }
    bar896();
    // gate combine (R9 seg-split order; c and bsum in registers)
    if (tid < 14){
      int j = tid, q = qbase + j;
      int half = j / 7, r = j % 7;
      float gsum[4];
#pragma unroll
      for (int g = 0; g < 4; g++){
        int ci = g*2 + half;
        float s = 0.f;
#pragma unroll
        for (int sgi = 0; sgi < 4; sgi++) s += sp[(ci*7 + r)*4 + sgi];
        gsum[g] = s;
      }
      int xr = (xrow < 0) ? sx[0] : xrow;
      const float* xp = d_xproj[xr];
      float gi = gsum[0] + __ldcg(xp + q)       + bs[0];
      float gf = gsum[1] + __ldcg(xp + q + H)   + bs[1];
      float gg = gsum[2] + __ldcg(xp + q + 2*H) + bs[2];
      float go = gsum[3] + __ldcg(xp + q + 3*H) + bs[3];
      float c2 = sigf(gf) * creg + sigf(gi) * tanhf(gg);
      float h2 = sigf(go) * tanhf(c2);
      creg = c2;
      d_hb[hp ^ 1][q] = h2;
    }
    // proj combine (R9)
    if (arow >= 0 && tid < 56){
      int c = tid / 7, r = tid % 7;
      const float* spP = sp + 56*4;
      float s = 0.f;
#pragma unroll
      for (int sgi = 0; sgi < 4; sgi++) s += spP[(c*7 + r)*4 + sgi];
      d_xproj[arow][pbase + c*7 + r] = s;
    }
  } else {
    // ---- block 0: control / sampling (R9 verbatim) ----
    if (attnL > 0){
      if (tid == 0){
        unsigned v;
        do { v = ldAcq(&d_acnt); } while ((int)(v - aneed) < 0);
      }
      bar896();
      if (wi < attnL){
        float a = 0.f;
        for (int k = lane; k < NBLK-1; k += 32) a += __ldcg(&d_blkpart[wi][k]);
#pragma unroll
        for (int o = 16; o; o >>= 1) a += __shfl_xor_sync(0xffffffffu, a, o);
        if (lane == 0) sl[wi] = a;
      }
      bar896();
      if (tid == 0){
        float lg[10];
        for (int i = 0; i < attnL; i++) lg[i] = 2.5f * tanhf(sl[i] / 5.0f);
        int idx = do_sample(attnL, lg);
        d_xrow = (idx < 2) ? 0 : (10 + idx - 2);
        p.out[arcpos] = (float)idx;
        stRel(&d_sflag, spub);
      }
    } else if (opsmp){
      if (wi < NBQ){
        float a = wdot(p.wsoft + (size_t)wi * H, shh, lane);
        if (lane == 0) sl[wi] = a;
      }
      bar896();
      if (tid == 0){
        float lg[NBQ];
        for (int i = 0; i < NBQ; i++){
          lg[i] = tanhf((sl[i] + p.bsoft[i]) / 5.0f);
          if (ub) lg[i] += p.bsnl[i];
        }
        int op = do_sample(NBQ, lg);
        d_xrow = 2 + op;
        p.out[arcpos] = (float)op;
        stRel(&d_sflag, spub);
      }
    }
  }

  // publish phase completion
  bar896();
  if (tid == 0) atomAddRel(&d_hcnt, 1u);
}

__global__ void __launch_bounds__(NTH, 1) ctrl_kernel(P p){
  extern __shared__ float shf[];
  char* smem = (char*)shf;
  int tid = threadIdx.x, wi = tid >> 5, lane = tid & 31;
  int b = blockIdx.x;
  unsigned gen   = *((volatile unsigned*)&g_flag);
  unsigned sbase = *((volatile unsigned*)&d_sflag);
  unsigned abase_cnt = *((volatile unsigned*)&d_acnt);
  unsigned hbase = *((volatile unsigned*)&d_hcnt);
  unsigned sc = 0, na = 0, hphase = 0;

  int qbase = (b > 0) ? min((b-1)*14, H - 14) : 0;
  int pbase = (b > 0) ? min((b-1)*56, G - 56) : 0;
  int awb   = (b > 0) ? min((b-1)*14, H - 14) : 0;

  uint32_t mb_full_base  = s2u(smem + OFF_MBAR);
  uint32_t mb_empty_base = s2u(smem + OFF_MBAR + 24);
  uint32_t buf_base      = s2u(smem + OFF_BUF);

  // ---- init ----
  if (tid == 0){
    for (int i = 0; i < NSLOT; i++){
      mbar_init(mb_full_base  + i*8, 1);
      mbar_init(mb_empty_base + i*8, NCW);
    }
  }
  for (int i = b*NTH + tid; i < H; i += NBLK*NTH){
    d_c[i] = 0.f; d_hb[0][i] = 0.f; d_hb[1][i] = 0.f;
  }
  for (int i = b*NTH + tid; i < G; i += NBLK*NTH){
    d_bsum[i] = p.bih[i] + p.bhh[i];
    d_xproj[0][i] = 0.f;
  }
  if (b == 0 && tid == 0){
    d_k0 = 0u; d_k1 = 42u;
    d_lp = 0.f; d_ent = 0.f;
  }
  // encoder rows -> smem (ring area, init only), project through W_ih
  {
    float* se = (float*)smem;
    for (int i = tid; i < 9*H; i += NTH) se[i] = p.enc[i];
    __syncthreads();
    int gwa = b * 29 + wi;
    for (int r = gwa; r < G; r += NWI){
      const float4* w4 = (const float4*)(p.wih + (size_t)r * H);
      float acc[9];
#pragma unroll
      for (int e = 0; e < 9; e++) acc[e] = 0.f;
      for (int t = 0; t < 16; t++){
        float4 wv = __ldg(w4 + lane + 32*t);
#pragma unroll
        for (int e = 0; e < 9; e++){
          float4 xv = ((const float4*)se)[e*512 + lane + 32*t];
          acc[e] += wv.x*xv.x + wv.y*xv.y + wv.z*xv.z + wv.w*xv.w;
        }
      }
      for (int e = 0; e < 9; e++){
        float a = acc[e];
#pragma unroll
        for (int o = 16; o; o >>= 1) a += __shfl_xor_sync(0xffffffffu, a, o);
        if (lane == 0) d_xproj[1 + e][r] = a;
      }
    }
  }
  // init grid barrier (all threads)
  __syncthreads();
  if (tid == 0){
    unsigned target = gen + 1u;
    unsigned old = atomAddRel(&g_count, 1u);
    if (old == (unsigned)(NBLK - 1)){
      stRelax(&g_count, 0u);
      stRel(&g_flag, target);
    } else {
      unsigned v;
      do { v = ldAcq(&g_flag); } while ((int)(v - target) < 0);
    }
  }
  gen += 1u;
  __syncthreads();

  // ================= producer warp (R9 verbatim) =================
  if (wi == 28){
    if (b > 0 && lane == 0){
      uint64_t polL = pol_evict_last();
      uint64_t polF = pol_evict_first();
      RC pc; pc.slot = 0; pc.ph = 1u;
      for (int s = 0; s < 2; s++){
        for (int ph = 0; ph < 42; ph++){
          int proj = 0;
          int k = ph - 2;
          if (k >= 0 && (k % 5) == 0){ int L = 2 + k/5; if (L >= 3) proj = 1; }
          for (int c = 0; c < 8; c++){
            uint32_t eb = mb_empty_base + pc.slot*8;
            uint32_t fb = mb_full_base  + pc.slot*8;
            mbar_wait_rlx(eb, pc.ph);
            mbar_expect_tx(fb, BUFB);
            const float* src = p.whh + (size_t)((c>>1)*2048 + qbase + (c&1)*7) * H;
            bulk_g2s_pol(buf_base + pc.slot*BUFB, src, BUFB, fb, polL);
            pc.adv();
          }
          if (proj){
            for (int c = 0; c < 8; c++){
              uint32_t eb = mb_empty_base + pc.slot*8;
              uint32_t fb = mb_full_base  + pc.slot*8;
              mbar_wait_rlx(eb, pc.ph);
              mbar_expect_tx(fb, BUFB);
              const float* src = p.wih + (size_t)(pbase + c*7) * H;
              bulk_g2s_pol(buf_base + pc.slot*BUFB, src, BUFB, fb, polF);
              pc.adv();
            }
          }
        }
      }
      for (int i = 0; i < NSLOT; i++){
        mbar_wait_rlx(mb_empty_base + pc.slot*8, pc.ph);
        pc.adv();
      }
    }
    return;
  }

  // ================= consumer warps (tid < 896) =================
  // registerized recurrent state (tid<14 of gate blocks)
  float creg = 0.f;
  float bs[4] = {0.f, 0.f, 0.f, 0.f};
  if (b > 0 && tid < 14){
    int q = qbase + tid;
    bs[0] = d_bsum[q];
    bs[1] = d_bsum[q + H];
    bs[2] = d_bsum[q + 2*H];
    bs[3] = d_bsum[q + 3*H];
  }

  RC rc; rc.slot = 0; rc.ph = 0u;
  int hp = 0;
  int p_ar = -2, p_ai = 0;
#define HNEED (hbase + 148u*hphase)
  for (int smp = 0; smp < 2; smp++){
    int ab = smp * 32;
    int ub = (smp == 0);
    mega(p, smem, b, tid, wi, lane, hp, -2, 0, 0, 0, 0, 1, 0, 0, 0, 0, HNEED,
         rc, qbase, pbase, awb, mb_full_base, mb_empty_base, creg, bs);
    hp ^= 1; hphase++;
    mega(p, smem, b, tid, wi, lane, hp, -1, 0, 0, 0, 0, 1, 0, 0, 0, 0, HNEED,
         rc, qbase, pbase, awb, mb_full_base, mb_empty_base, creg, bs);
    hp ^= 1; hphase++;
    p_ar = -1; p_ai = 1;
    for (int L = 2; L <= 9; L++){
      int base = ab + (L - 2) * 4;
      // ph1: cell (enc0) + pending proj/aw1
      mega(p, smem, b, tid, wi, lane, hp, p_ar, p_ai, 0, 0, 0, 1, 0, 0, 0, 0, HNEED,
           rc, qbase, pbase, awb, mb_full_base, mb_empty_base, creg, bs);
      hp ^= 1; hphase++;
      // ph2: cell + attn(h1); b0 samples idx0
      sc++; na++;
      mega(p, smem, b, tid, wi, lane, hp, -2, 0, L, 0, 0, -1, sbase + sc,
           base + 0, sbase + sc, abase_cnt + (NBLK-1)*na, HNEED,
           rc, qbase, pbase, awb, mb_full_base, mb_empty_base, creg, bs);
      hp ^= 1; hphase++;
      // ph3: cell + attn(h2); b0 samples idx1
      sc++; na++;
      mega(p, smem, b, tid, wi, lane, hp, -2, 0, L, 0, 0, -1, sbase + sc,
           base + 2, sbase + sc, abase_cnt + (NBLK-1)*na, HNEED,
           rc, qbase, pbase, awb, mb_full_base, mb_empty_base, creg, bs);
      hp ^= 1; hphase++;
      // ph4: cell; b0 samples op0 from h3
      sc++;
      mega(p, smem, b, tid, wi, lane, hp, -2, 0, 0, 1, ub, -1, sbase + sc,
           base + 1, sbase + sc, 0, HNEED,
           rc, qbase, pbase, awb, mb_full_base, mb_empty_base, creg, bs);
      hp ^= 1; hphase++;
      // ph5: anchor cell; b0 samples op1 from h4
      sc++;
      mega(p, smem, b, tid, wi, lane, hp, -2, 0, 0, 1, ub, -1, sbase + sc,
           base + 3, sbase + sc, 0, HNEED,
           rc, qbase, pbase, awb, mb_full_base, mb_empty_base, creg, bs);
      hp ^= 1; hphase++;
      if (L < 9){ p_ar = 10 + (L - 2); p_ai = L; }
      else      { p_ar = -2; p_ai = 0; }
    }
  }
#undef HNEED

  if (b == 0 && tid == 0){
    p.out[64] = d_lp;
    p.out[65] = d_ent;
  }
}

extern "C" void kernel_launch(void* const* d_in, const int* in_sizes, int n_in,
                              void* d_out, int out_size){
  P p;
  p.enc   = (const float*)d_in[0];
  p.wih   = (const float*)d_in[1];
  p.bih   = (const float*)d_in[2];
  p.whh   = (const float*)d_in[3];
  p.bhh   = (const float*)d_in[4];
  p.wsoft = (const float*)d_in[5];
  p.bsoft = (const float*)d_in[6];
  p.bsnl  = (const float*)d_in[7];
  p.w1    = (const float*)d_in[8];
  p.w2    = (const float*)d_in[9];
  p.v     = (const float*)d_in[10];
  p.out   = (float*)d_out;
  (void)in_sizes; (void)n_in; (void)out_size;

  cudaFuncSetAttribute(ctrl_kernel, cudaFuncAttributeMaxDynamicSharedMemorySize, SMEM_SZ);
  ctrl_kernel<<<NBLK, NTH, SMEM_SZ>>>(p);
}